// round 4
// baseline (speedup 1.0000x reference)
#include <cuda_runtime.h>
#include <math.h>

#define N_NODES 50000
#define N_EDGES 1600000
#define D 128
#define BN_EPS 1e-5f

// ---------------- device scratch (no allocations allowed) ----------------
__device__ __align__(16) float g_h[N_NODES * D];    // layer input (post BN+ReLU)
__device__ __align__(16) float g_hw[N_NODES * D];   // h @ W
__device__ __align__(16) float g_hws[N_NODES * D];  // hw * dinv[row]
__device__ __align__(16) float g_agg[N_NODES * D];  // pre-BN activations
__device__ int   g_src[N_EDGES];
__device__ int   g_dst[N_EDGES];
__device__ int   g_is_i32;                          // dtype detection flag
__device__ int   g_deg[N_NODES];
__device__ int   g_rowstart[N_NODES + 1];
__device__ int   g_cursor[N_NODES];
__device__ int   g_csr_src[N_EDGES];
__device__ float g_dinv[N_NODES];                   // rsqrt(deg+2)
__device__ float g_selfw[N_NODES];                  // 2/(deg+2)
__device__ float g_colsum[D];
__device__ float g_colsq[D];
__device__ float g_scale[D];
__device__ float g_shift[D];

// ---------------- input canonicalization ----------------
// If edge_index is int64 (little-endian, values < 2^31), every odd 32-bit word
// of the first N_EDGES int64 slots is 0. If it's int32, those words are real
// random indices (virtually surely nonzero somewhere over 1.6M samples).

__global__ void detect_kernel(const int* __restrict__ p32) {
    if (blockIdx.x == 0 && threadIdx.x == 0) g_is_i32 = 0;
    __threadfence();
    int e = blockIdx.x * blockDim.x + threadIdx.x;
    if (e < N_EDGES) {
        if (p32[2 * e + 1] != 0) g_is_i32 = 1;   // racy write of same value: fine
    }
}

__global__ void convert_kernel(const void* __restrict__ eiv) {
    int e = blockIdx.x * blockDim.x + threadIdx.x;
    if (e >= N_EDGES) return;
    if (g_is_i32) {
        const int* p = (const int*)eiv;
        g_src[e] = p[e];
        g_dst[e] = p[N_EDGES + e];
    } else {
        const long long* p = (const long long*)eiv;
        g_src[e] = (int)p[e];
        g_dst[e] = (int)p[N_EDGES + e];
    }
}

// ---------------- graph preprocessing (once per launch) ----------------

__global__ void zero_deg_kernel() {
    int i = blockIdx.x * blockDim.x + threadIdx.x;
    if (i < N_NODES) g_deg[i] = 0;
}

__global__ void deg_count_kernel() {
    int e = blockIdx.x * blockDim.x + threadIdx.x;
    if (e < N_EDGES) atomicAdd(&g_deg[g_dst[e]], 1);
}

// single-block exclusive scan of g_deg -> g_rowstart (and total at [N_NODES])
__global__ void scan_kernel() {
    __shared__ int warpsum[32];
    __shared__ int s_carry;
    const int tid = threadIdx.x, lane = tid & 31, wid = tid >> 5;
    if (tid == 0) s_carry = 0;
    __syncthreads();

    for (int base = 0; base < N_NODES; base += 1024) {
        int i = base + tid;
        int v = (i < N_NODES) ? g_deg[i] : 0;
        int x = v;
#pragma unroll
        for (int off = 1; off < 32; off <<= 1) {
            int n = __shfl_up_sync(0xffffffffu, x, off);
            if (lane >= off) x += n;
        }
        if (lane == 31) warpsum[wid] = x;
        __syncthreads();
        if (wid == 0) {
            int w = warpsum[lane];
#pragma unroll
            for (int off = 1; off < 32; off <<= 1) {
                int n = __shfl_up_sync(0xffffffffu, w, off);
                if (lane >= off) w += n;
            }
            warpsum[lane] = w;  // inclusive scan of warp sums
        }
        __syncthreads();
        int wprefix = (wid == 0) ? 0 : warpsum[wid - 1];
        int incl = x + wprefix;
        int carry = s_carry;
        if (i < N_NODES) g_rowstart[i] = carry + incl - v;  // exclusive
        int total = warpsum[31];
        __syncthreads();  // everyone read s_carry/warpsum before update
        if (tid == 0) s_carry = carry + total;
        __syncthreads();
    }
    if (tid == 0) g_rowstart[N_NODES] = s_carry;
}

__global__ void deg_final_kernel() {
    int i = blockIdx.x * blockDim.x + threadIdx.x;
    if (i < N_NODES) {
        float d = (float)g_deg[i] + 2.0f;
        g_dinv[i] = rsqrtf(d);
        g_selfw[i] = 2.0f / d;
        g_cursor[i] = g_rowstart[i];
    }
}

__global__ void fill_kernel() {
    int e = blockIdx.x * blockDim.x + threadIdx.x;
    if (e < N_EDGES) {
        int p = atomicAdd(&g_cursor[g_dst[e]], 1);
        g_csr_src[p] = g_src[e];
    }
}

// ---------------- per-layer kernels ----------------

// hw = A @ W, hws = hw * dinv[row].  block: 128 threads (one per col), 32 rows.
__global__ void gemm_kernel(const float* __restrict__ A, const float* __restrict__ W,
                            int use_gh) {
    __shared__ float shA[32][D];
    const int rb = blockIdx.x * 32;
    const int t = threadIdx.x;  // column 0..127
    const float* __restrict__ src = use_gh ? g_h : A;

#pragma unroll
    for (int r = 0; r < 32; r++) {
        int row = rb + r;
        shA[r][t] = (row < N_NODES) ? src[row * D + t] : 0.0f;
    }
    __syncthreads();

    float acc[32];
#pragma unroll
    for (int r = 0; r < 32; r++) acc[r] = 0.0f;

    for (int k = 0; k < D; k++) {
        float w = W[k * D + t];
#pragma unroll
        for (int r = 0; r < 32; r++) acc[r] += shA[r][k] * w;
    }

#pragma unroll
    for (int r = 0; r < 32; r++) {
        int row = rb + r;
        if (row < N_NODES) {
            g_hw[row * D + t] = acc[r];
            g_hws[row * D + t] = acc[r] * g_dinv[row];
        }
    }
}

// one block per node (128 threads, thread = column): CSR gather
__global__ void aggregate_kernel(const float* __restrict__ b) {
    const int node = blockIdx.x;
    const int c = threadIdx.x;
    const int beg = g_rowstart[node];
    const int end = g_rowstart[node + 1];

    float acc = 0.0f;
    for (int k = beg; k < end; k++) {
        int s = g_csr_src[k];  // same addr across warp -> broadcast
        acc += g_hws[s * D + c];
    }
    float v = g_dinv[node] * acc + g_selfw[node] * g_hw[node * D + c] + b[c];
    g_agg[node * D + c] = v;
}

__global__ void zero_stats_kernel() {
    int c = threadIdx.x;
    g_colsum[c] = 0.0f;
    g_colsq[c] = 0.0f;
}

// column sums/sumsq over g_agg; block handles 128 rows
__global__ void stats_kernel() {
    const int c = threadIdx.x;
    const int r0 = blockIdx.x * 128;
    float s = 0.0f, sq = 0.0f;
    for (int i = 0; i < 128; i++) {
        int r = r0 + i;
        if (r >= N_NODES) break;
        float v = g_agg[r * D + c];
        s += v;
        sq += v * v;
    }
    atomicAdd(&g_colsum[c], s);
    atomicAdd(&g_colsq[c], sq);
}

__global__ void bn_final_kernel(const float* __restrict__ gamma,
                                const float* __restrict__ beta) {
    int c = threadIdx.x;
    float mean = g_colsum[c] * (1.0f / (float)N_NODES);
    float var = g_colsq[c] * (1.0f / (float)N_NODES) - mean * mean;
    float sc = gamma[c] * rsqrtf(var + BN_EPS);
    g_scale[c] = sc;
    g_shift[c] = beta[c] - mean * sc;
}

// y = relu(agg*scale + shift); out!=nullptr -> final output, else next input
__global__ void apply_kernel(float* out) {
    int idx = blockIdx.x * blockDim.x + threadIdx.x;
    if (idx >= N_NODES * D) return;
    int c = idx & (D - 1);
    float v = g_agg[idx] * g_scale[c] + g_shift[c];
    v = fmaxf(v, 0.0f);
    if (out) out[idx] = v;
    else     g_h[idx] = v;
}

// ---------------- launch ----------------
extern "C" void kernel_launch(void* const* d_in, const int* in_sizes, int n_in,
                              void* d_out, int out_size) {
    const float* x = (const float*)d_in[0];
    const void* ei = d_in[1];
    const float* W[3]  = {(const float*)d_in[2],  (const float*)d_in[6],  (const float*)d_in[10]};
    const float* bb[3] = {(const float*)d_in[3],  (const float*)d_in[7],  (const float*)d_in[11]};
    const float* gg[3] = {(const float*)d_in[4],  (const float*)d_in[8],  (const float*)d_in[12]};
    const float* be[3] = {(const float*)d_in[5],  (const float*)d_in[9],  (const float*)d_in[13]};
    float* out = (float*)d_out;

    const int eblocks = (N_EDGES + 255) / 256;
    const int nblocks = (N_NODES + 255) / 256;

    // canonicalize edge_index (handles both int32 and int64 harness layouts)
    detect_kernel<<<eblocks, 256>>>((const int*)ei);
    convert_kernel<<<eblocks, 256>>>(ei);

    // CSR build (edges identical across layers)
    zero_deg_kernel<<<nblocks, 256>>>();
    deg_count_kernel<<<eblocks, 256>>>();
    scan_kernel<<<1, 1024>>>();
    deg_final_kernel<<<nblocks, 256>>>();
    fill_kernel<<<eblocks, 256>>>();

    const int gemm_blocks = (N_NODES + 31) / 32;
    const int stats_blocks = (N_NODES + 127) / 128;
    const int app_blocks = (N_NODES * D + 255) / 256;

    for (int layer = 0; layer < 3; layer++) {
        gemm_kernel<<<gemm_blocks, 128>>>(x, W[layer], layer != 0);
        aggregate_kernel<<<N_NODES, 128>>>(bb[layer]);
        zero_stats_kernel<<<1, D>>>();
        stats_kernel<<<stats_blocks, 128>>>();
        bn_final_kernel<<<1, D>>>(gg[layer], be[layer]);
        apply_kernel<<<app_blocks, 256>>>(layer == 2 ? out : (float*)nullptr);
    }
}

// round 5
// speedup vs baseline: 1.5093x; 1.5093x over previous
#include <cuda_runtime.h>
#include <math.h>

#define N_NODES 50000
#define N_EDGES 1600000
#define D 128
#define BN_EPS 1e-5f

// ---------------- device scratch (no allocations allowed) ----------------
__device__ __align__(16) float g_hws[N_NODES * D];  // (h @ W) * dinv[row]
__device__ __align__(16) float g_agg[N_NODES * D];  // pre-BN activations
__device__ int   g_src[N_EDGES];
__device__ int   g_dst[N_EDGES];
__device__ int   g_is_i32 = 0;                      // set-only dtype flag (static init)
__device__ int   g_deg[N_NODES];
__device__ int   g_rowstart[N_NODES + 1];
__device__ int   g_cursor[N_NODES];
__device__ int   g_csr_src[N_EDGES];
__device__ float g_dinv[N_NODES];                   // rsqrt(deg+2)
__device__ float g_colsum[D];
__device__ float g_colsq[D];
__device__ float g_scale[D];
__device__ float g_shift[D];

// ---------------- input canonicalization + degree zero ----------------
// int64 little-endian with values<2^31 -> every odd 32-bit word of the first
// N_EDGES slots is 0. int32 -> those words are random nonzero indices.
// g_is_i32 is statically 0 and only ever set to 1 (race-free, replay-stable).
__global__ void detect_kernel(const int* __restrict__ p32) {
    int e = blockIdx.x * blockDim.x + threadIdx.x;
    if (e < N_NODES) g_deg[e] = 0;
    if (e < N_EDGES && p32[2 * e + 1] != 0) g_is_i32 = 1;
}

__global__ void convert_count_kernel(const void* __restrict__ eiv) {
    int e = blockIdx.x * blockDim.x + threadIdx.x;
    if (e >= N_EDGES) return;
    int s, d;
    if (g_is_i32) {
        const int* p = (const int*)eiv;
        s = p[e]; d = p[N_EDGES + e];
    } else {
        const long long* p = (const long long*)eiv;
        s = (int)p[e]; d = (int)p[N_EDGES + e];
    }
    g_src[e] = s;
    g_dst[e] = d;
    atomicAdd(&g_deg[d], 1);
}

// single-block exclusive scan of g_deg -> g_rowstart; then dinv/cursor tail
__global__ void scan_final_kernel() {
    __shared__ int warpsum[32];
    __shared__ int s_carry;
    const int tid = threadIdx.x, lane = tid & 31, wid = tid >> 5;
    if (tid == 0) s_carry = 0;
    __syncthreads();

    for (int base = 0; base < N_NODES; base += 1024) {
        int i = base + tid;
        int v = (i < N_NODES) ? g_deg[i] : 0;
        int x = v;
#pragma unroll
        for (int off = 1; off < 32; off <<= 1) {
            int n = __shfl_up_sync(0xffffffffu, x, off);
            if (lane >= off) x += n;
        }
        if (lane == 31) warpsum[wid] = x;
        __syncthreads();
        if (wid == 0) {
            int w = warpsum[lane];
#pragma unroll
            for (int off = 1; off < 32; off <<= 1) {
                int n = __shfl_up_sync(0xffffffffu, w, off);
                if (lane >= off) w += n;
            }
            warpsum[lane] = w;
        }
        __syncthreads();
        int wprefix = (wid == 0) ? 0 : warpsum[wid - 1];
        int carry = s_carry;
        if (i < N_NODES) g_rowstart[i] = carry + x + wprefix - v;  // exclusive
        int total = warpsum[31];
        __syncthreads();
        if (tid == 0) s_carry = carry + total;
        __syncthreads();
    }
    if (tid == 0) g_rowstart[N_NODES] = s_carry;
    __syncthreads();
    for (int i = tid; i < N_NODES; i += 1024) {
        float dd = (float)g_deg[i] + 2.0f;
        g_dinv[i] = rsqrtf(dd);
        g_cursor[i] = g_rowstart[i];
    }
}

__global__ void fill_kernel() {
    int e = blockIdx.x * blockDim.x + threadIdx.x;
    if (e < N_EDGES) {
        int p = atomicAdd(&g_cursor[g_dst[e]], 1);
        g_csr_src[p] = g_src[e];
    }
}

// ---------------- per-layer kernels ----------------

// hws = f(src) @ W * dinv[row].  mode 0: f = identity on x.
// mode 1: f = ReLU(g_agg*scale+shift) (fused BN apply of previous layer).
// Block: 128 threads (one per column), 32 rows. Block 0 also zeroes BN stats.
__global__ void gemm_kernel(const float* __restrict__ A, const float* __restrict__ W,
                            int mode) {
    __shared__ __align__(16) float shA[32][D];
    const int rb = blockIdx.x * 32;
    const int t = threadIdx.x;  // column 0..127

    float sc = 0.0f, sh = 0.0f;
    if (mode) { sc = g_scale[t]; sh = g_shift[t]; }

#pragma unroll
    for (int r = 0; r < 32; r++) {
        int row = rb + r;
        float v = 0.0f;
        if (row < N_NODES) {
            if (mode) {
                v = g_agg[row * D + t];
                v = fmaxf(v * sc + sh, 0.0f);
            } else {
                v = A[row * D + t];
            }
        }
        shA[r][t] = v;
    }
    if (blockIdx.x == 0) { g_colsum[t] = 0.0f; g_colsq[t] = 0.0f; }
    __syncthreads();

    float acc[32];
#pragma unroll
    for (int r = 0; r < 32; r++) acc[r] = 0.0f;

    const float4* shA4 = reinterpret_cast<const float4*>(&shA[0][0]);
#pragma unroll 4
    for (int k4 = 0; k4 < D / 4; k4++) {
        float4 w4;
        w4.x = W[(4 * k4 + 0) * D + t];
        w4.y = W[(4 * k4 + 1) * D + t];
        w4.z = W[(4 * k4 + 2) * D + t];
        w4.w = W[(4 * k4 + 3) * D + t];
#pragma unroll
        for (int r = 0; r < 32; r++) {
            float4 a = shA4[r * (D / 4) + k4];
            acc[r] += a.x * w4.x;
            acc[r] += a.y * w4.y;
            acc[r] += a.z * w4.z;
            acc[r] += a.w * w4.w;
        }
    }

#pragma unroll
    for (int r = 0; r < 32; r++) {
        int row = rb + r;
        if (row < N_NODES) g_hws[row * D + t] = acc[r] * g_dinv[row];
    }
}

// warp per node; lane owns 4 columns (float4). Indices prefetched 32 at a
// time with a coalesced load and shfl-broadcast.
__global__ void aggregate_kernel(const float* __restrict__ b) {
    const int node = blockIdx.x * 8 + (threadIdx.x >> 5);
    const int lane = threadIdx.x & 31;
    if (node >= N_NODES) return;

    const int beg = g_rowstart[node];
    const int end = g_rowstart[node + 1];
    const float4* __restrict__ hws4 = reinterpret_cast<const float4*>(g_hws);

    float4 acc = make_float4(0.0f, 0.0f, 0.0f, 0.0f);
    for (int k0 = beg; k0 < end; k0 += 32) {
        int t = k0 + lane;
        int idx = (t < end) ? g_csr_src[t] : 0;
        int m = min(32, end - k0);
#pragma unroll 8
        for (int j = 0; j < m; j++) {
            int s = __shfl_sync(0xffffffffu, idx, j);
            float4 v = hws4[s * 32 + lane];
            acc.x += v.x; acc.y += v.y; acc.z += v.z; acc.w += v.w;
        }
    }

    float4 self = hws4[node * 32 + lane];
    float dinv = g_dinv[node];
    float4 b4 = reinterpret_cast<const float4*>(b)[lane];
    float4 o;
    o.x = dinv * (acc.x + 2.0f * self.x) + b4.x;
    o.y = dinv * (acc.y + 2.0f * self.y) + b4.y;
    o.z = dinv * (acc.z + 2.0f * self.z) + b4.z;
    o.w = dinv * (acc.w + 2.0f * self.w) + b4.w;
    reinterpret_cast<float4*>(g_agg)[node * 32 + lane] = o;
}

// column sums/sumsq over g_agg; block handles 128 rows (thread = column)
__global__ void stats_kernel() {
    const int c = threadIdx.x;
    const int r0 = blockIdx.x * 128;
    float s = 0.0f, sq = 0.0f;
    for (int i = 0; i < 128; i++) {
        int r = r0 + i;
        if (r >= N_NODES) break;
        float v = g_agg[r * D + c];
        s += v;
        sq += v * v;
    }
    atomicAdd(&g_colsum[c], s);
    atomicAdd(&g_colsq[c], sq);
}

__global__ void bn_final_kernel(const float* __restrict__ gamma,
                                const float* __restrict__ beta) {
    int c = threadIdx.x;
    float mean = g_colsum[c] * (1.0f / (float)N_NODES);
    float var = g_colsq[c] * (1.0f / (float)N_NODES) - mean * mean;
    float sc = gamma[c] * rsqrtf(var + BN_EPS);
    g_scale[c] = sc;
    g_shift[c] = beta[c] - mean * sc;
}

// final layer only: out = relu(agg*scale + shift)
__global__ void apply_kernel(float* __restrict__ out) {
    int idx = blockIdx.x * blockDim.x + threadIdx.x;
    if (idx >= N_NODES * D) return;
    int c = idx & (D - 1);
    float v = g_agg[idx] * g_scale[c] + g_shift[c];
    out[idx] = fmaxf(v, 0.0f);
}

// ---------------- launch ----------------
extern "C" void kernel_launch(void* const* d_in, const int* in_sizes, int n_in,
                              void* d_out, int out_size) {
    const float* x = (const float*)d_in[0];
    const void* ei = d_in[1];
    const float* W[3]  = {(const float*)d_in[2],  (const float*)d_in[6],  (const float*)d_in[10]};
    const float* bb[3] = {(const float*)d_in[3],  (const float*)d_in[7],  (const float*)d_in[11]};
    const float* gg[3] = {(const float*)d_in[4],  (const float*)d_in[8],  (const float*)d_in[12]};
    const float* be[3] = {(const float*)d_in[5],  (const float*)d_in[9],  (const float*)d_in[13]};
    float* out = (float*)d_out;

    const int eblocks = (N_EDGES + 255) / 256;

    detect_kernel<<<eblocks, 256>>>((const int*)ei);          // 1
    convert_count_kernel<<<eblocks, 256>>>(ei);               // 2
    scan_final_kernel<<<1, 1024>>>();                         // 3
    fill_kernel<<<eblocks, 256>>>();                          // 4

    const int gemm_blocks = (N_NODES + 31) / 32;
    const int agg_blocks = (N_NODES + 7) / 8;
    const int stats_blocks = (N_NODES + 127) / 128;
    const int app_blocks = (N_NODES * D + 255) / 256;

    for (int layer = 0; layer < 3; layer++) {
        gemm_kernel<<<gemm_blocks, 128>>>(x, W[layer], layer != 0);  // 5 (L0)
        aggregate_kernel<<<agg_blocks, 256>>>(bb[layer]);            // 6 (L0) <- ncu -s 5
        stats_kernel<<<stats_blocks, 128>>>();
        bn_final_kernel<<<1, D>>>(gg[layer], be[layer]);
    }
    apply_kernel<<<app_blocks, 256>>>(out);
}